// round 12
// baseline (speedup 1.0000x reference)
#include <cuda_runtime.h>
#include <cstdint>

#define T_DIM   16
#define M_DIM   1024
#define K_DIM   4096
#define N_NODES 10000
#define N_IN    8000
#define N_B     100
#define NPC     64            // nodes per CTA -> 128 A-rows
#define NCHUNK  64            // K chunks of 64
#define DYNSZ   (64 * 1024)   // 2 bufs x (Ah 16KB + Al 16KB)

typedef unsigned long long u64;

// Scratch (zero-initialized; mark/compact idempotent across graph replays)
__device__ float g_f[N_NODES * 32];          // f[n][t][o]
__device__ int   g_mask[N_NODES];
__device__ int   g_list[N_NODES];
__device__ int   g_count;
__device__ uint4 g_xfrag[256 * 2 * 32];      // [ks][ntile][lane] = {b0h,b1h,b0l,b1l}

__device__ __forceinline__ uint32_t s2u(const void* p) {
    uint32_t a;
    asm("{ .reg .u64 t; cvta.to.shared.u64 t, %1; cvt.u32.u64 %0, t; }" : "=r"(a) : "l"(p));
    return a;
}
__device__ __forceinline__ uint32_t bf2(float hi, float lo) {   // bf16(hi)<<16 | bf16(lo)
    uint32_t d;
    asm("cvt.rn.bf16x2.f32 %0, %1, %2;" : "=r"(d) : "f"(hi), "f"(lo));
    return d;
}
__device__ __forceinline__ float hi16f(uint32_t w) { return __uint_as_float(w & 0xffff0000u); }
__device__ __forceinline__ float lo16f(uint32_t w) { return __uint_as_float(w << 16); }
__device__ __forceinline__ void sts32(uint32_t a, uint32_t v) {
    asm volatile("st.shared.b32 [%0], %1;" :: "r"(a), "r"(v) : "memory");
}
__device__ __forceinline__ void ldsm4(uint32_t& r0, uint32_t& r1, uint32_t& r2, uint32_t& r3,
                                      uint32_t addr) {
    asm volatile("ldmatrix.sync.aligned.m8n8.x4.shared.b16 {%0,%1,%2,%3}, [%4];"
                 : "=r"(r0), "=r"(r1), "=r"(r2), "=r"(r3) : "r"(addr));
}
__device__ __forceinline__ void mmabf(float d[4], uint32_t a0, uint32_t a1, uint32_t a2,
                                      uint32_t a3, uint32_t b0, uint32_t b1) {
    asm volatile("mma.sync.aligned.m16n8k16.row.col.f32.bf16.bf16.f32 "
                 "{%0,%1,%2,%3}, {%4,%5,%6,%7}, {%8,%9}, {%0,%1,%2,%3};"
                 : "+f"(d[0]), "+f"(d[1]), "+f"(d[2]), "+f"(d[3])
                 : "r"(a0), "r"(a1), "r"(a2), "r"(a3), "r"(b0), "r"(b1));
}
// swizzled byte offset inside a 128-rows x 128B A tile (16B-chunk XOR by row&7)
__device__ __forceinline__ uint32_t swz(uint32_t row, uint32_t bc) {
    return row * 128u + ((((bc >> 4) ^ (row & 7u)) << 4) | (bc & 15u));
}
__device__ __forceinline__ float xval(const float* __restrict__ x, int t, int i) {
    int m = i >> 2, j = i & 3;
    int p = (j == 0) ? 0 : ((j == 3) ? 1 : 2);   // [x0, x2, x2, x1]
    return x[(t * 3 + p) * M_DIM + m];
}

// ---- 1) prep: build x B-fragments (mma layout, bf16 hi/lo); mark+compact nodes ----
__global__ void k_prep(const float* __restrict__ x,
                       const int* __restrict__ node_in,
                       const int* __restrict__ top, const int* __restrict__ bottom,
                       const int* __restrict__ left, const int* __restrict__ right) {
    if (blockIdx.x < 64) {
        int id = blockIdx.x * 256 + threadIdx.x;   // 16384 = 256 ks * 2 ntile * 32 lanes
        int ks = id >> 6;
        int ln = id & 31;
        int t  = ((id >> 5) & 1) * 8 + (ln >> 2);  // n index = t
        int k0 = ks * 16 + 2 * (ln & 3);
        float v0 = xval(x, t, k0),     v1 = xval(x, t, k0 + 1);
        float v8 = xval(x, t, k0 + 8), v9 = xval(x, t, k0 + 9);
        uint32_t b0h = bf2(v1, v0);
        uint32_t b1h = bf2(v9, v8);
        uint32_t b0l = bf2(v1 - hi16f(b0h), v0 - lo16f(b0h));
        uint32_t b1l = bf2(v9 - hi16f(b1h), v8 - lo16f(b1h));
        g_xfrag[id] = make_uint4(b0h, b1h, b0l, b1l);
    } else {
        int idx = (blockIdx.x - 64) * 256 + threadIdx.x;
        int v = 0;
        if      (idx < N_IN)           v = node_in[idx];
        else if (idx < N_IN + 1*N_B)   v = top[idx - N_IN];
        else if (idx < N_IN + 2*N_B)   v = bottom[idx - N_IN - 1*N_B];
        else if (idx < N_IN + 3*N_B)   v = left[idx - N_IN - 2*N_B];
        else if (idx < N_IN + 4*N_B)   v = right[idx - N_IN - 3*N_B];
        if (v > 0 && atomicExch(&g_mask[v - 1], 1) == 0)
            g_list[atomicAdd(&g_count, 1)] = v - 1;
    }
}

// ---- 2) HMMA GEMM, 3-term bf16 split ----
// smem: buf b: Ah @ b*32K, Al @ b*32K+16K. Tile = 128 rows x 64 bf16 cols (128B/row).
__global__ void __launch_bounds__(256)
k_mma(const float* __restrict__ weight) {
    extern __shared__ __align__(16) char dynraw[];
    const int count = g_count;
    const int base = blockIdx.x * NPC;
    if (base >= count) return;

    const int tid = threadIdx.x;
    const int nodesHere = (count - base < NPC) ? (count - base) : NPC;
    const int nl = tid >> 2, sub = tid & 3;          // 4 threads stage one node (2 rows)
    const int node = g_list[base + (nl < nodesHere ? nl : nodesHere - 1)];
    // weight row = 4096*2 floats = 2048 float4  (R10 bug: was node*1024)
    const float4* __restrict__ w4 = (const float4*)weight + (size_t)node * 2048;
    const uint32_t smem = s2u(dynraw);
    const int wrp = tid >> 5, lane = tid & 31;

    float acc[2][4] = {{0.f,0.f,0.f,0.f},{0.f,0.f,0.f,0.f}};
    float4 rA[8], rB[8];
    #pragma unroll
    for (int u = 0; u < 8; ++u) rA[u] = __ldcs(w4 + sub * 8 + u);   // chunk 0

    // ldmatrix lane geometry (constant over chunks)
    const int m      = lane >> 3;
    const uint32_t lrow = (uint32_t)(wrp * 16 + ((m & 1) << 3) + (lane & 7));
    const int kbofs  = m >> 1;

    #pragma unroll 1
    for (int c = 0; c < NCHUNK; ++c) {
        const int buf = c & 1;
        const int cn = (c + 1 < NCHUNK) ? c + 1 : c;
        #pragma unroll
        for (int u = 0; u < 8; ++u) rB[u] = __ldcs(w4 + cn * 32 + sub * 8 + u);

        // convert + store rA (chunk c) into buffer
        const uint32_t aH = smem + (uint32_t)buf * 32768u;
        const uint32_t aL = aH + 16384u;
        const uint32_t r0 = (uint32_t)(2 * nl);
        #pragma unroll
        for (int u = 0; u < 8; ++u) {                // f = (w[i][0],w[i][1],w[i+1][0],w[i+1][1])
            float4 f = rA[u];
            uint32_t bc = (uint32_t)(sub * 32 + 4 * u);
            uint32_t h0 = bf2(f.z, f.x);
            uint32_t l0 = bf2(f.z - hi16f(h0), f.x - lo16f(h0));
            uint32_t h1 = bf2(f.w, f.y);
            uint32_t l1 = bf2(f.w - hi16f(h1), f.y - lo16f(h1));
            uint32_t o0 = swz(r0, bc), o1 = swz(r0 + 1, bc);
            sts32(aH + o0, h0); sts32(aL + o0, l0);
            sts32(aH + o1, h1); sts32(aL + o1, l1);
        }
        __syncthreads();     // single sync/chunk: 2 buffers make this hazard-free

        // MMA: warp owns rows 16*wrp..16*wrp+15
        #pragma unroll
        for (int ks = 0; ks < 4; ++ks) {
            uint32_t adr = aH + swz(lrow, (uint32_t)((2 * ks + kbofs) << 4));
            uint32_t a0, a1, a2, a3, q0, q1, q2, q3;
            ldsm4(a0, a1, a2, a3, adr);              // Ah fragment
            ldsm4(q0, q1, q2, q3, adr + 16384u);     // Al fragment
            #pragma unroll
            for (int nt = 0; nt < 2; ++nt) {
                uint4 bf = g_xfrag[(c * 4 + ks) * 64 + nt * 32 + lane];
                mmabf(acc[nt], a0, a1, a2, a3, bf.x, bf.y);   // Ah*Bh
                mmabf(acc[nt], a0, a1, a2, a3, bf.z, bf.w);   // Ah*Bl
                mmabf(acc[nt], q0, q1, q2, q3, bf.x, bf.y);   // Al*Bh
            }
        }
        #pragma unroll
        for (int u = 0; u < 8; ++u) rA[u] = rB[u];
    }

    // epilogue: D fragment -> g_f.  d0,d1: row g, cols 2t2,2t2+1; d2,d3: row g+8
    const int g = lane >> 2, t2 = lane & 3;
    #pragma unroll
    for (int half = 0; half < 2; ++half) {
        int row = wrp * 16 + g + half * 8;
        int rnl = row >> 1, o = row & 1;
        int nd = g_list[base + (rnl < nodesHere ? rnl : nodesHere - 1)];
        #pragma unroll
        for (int nt = 0; nt < 2; ++nt) {
            int t = nt * 8 + 2 * t2;
            g_f[nd * 32 + 2 * t + o]       = acc[nt][half * 2 + 0];
            g_f[nd * 32 + 2 * (t + 1) + o] = acc[nt][half * 2 + 1];
        }
    }
}

// ---- 3) epilogue: ILP-8 gather (blocks 0..31) + parallel boundary sums (block 32) ----
__global__ void k_post(const int* __restrict__ node_in,
                       const int* __restrict__ top, const int* __restrict__ bottom,
                       const int* __restrict__ left, const int* __restrict__ right,
                       float* __restrict__ out) {
    if (blockIdx.x < 32) {
        int k = blockIdx.x * 256 + threadIdx.x;
        if (k < N_IN) {
            const float4* __restrict__ src = (const float4*)g_f + (size_t)(node_in[k] - 1) * 8;
            float4* __restrict__ dst = (float4*)out + (size_t)k * 8;
            float4 v0 = src[0], v1 = src[1], v2 = src[2], v3 = src[3];
            float4 v4 = src[4], v5 = src[5], v6 = src[6], v7 = src[7];
            dst[0] = v0; dst[1] = v1; dst[2] = v2; dst[3] = v3;
            dst[4] = v4; dst[5] = v5; dst[6] = v6; dst[7] = v7;
        }
    } else {
        __shared__ float s[4][4][16];
        const int tid = threadIdx.x;
        const int ch = tid >> 6, rt = tid & 63, r = rt >> 4, t = rt & 15;
        const int* arr = (r == 0) ? top : (r == 1) ? bottom : (r == 2) ? left : right;
        const int o = (r < 2) ? 1 : 0;
        float sum = 0.0f;
        #pragma unroll
        for (int b = 25 * ch; b < 25 * ch + 25; ++b)
            sum += g_f[(arr[b] - 1) * 32 + t * 2 + o];
        s[ch][r][t] = sum;
        __syncthreads();
        float* ob = out + N_IN * 32;
        if (tid < 64) {
            float v = s[0][r][t] + s[1][r][t] + s[2][r][t] + s[3][r][t];
            s[0][r][t] = v;
            ob[r * 16 + t] = v;
        }
        __syncthreads();
        if (tid < 32) {
            int rr = tid >> 4, tt = tid & 15;        // 0: top+bottom, 1: left+right
            ob[(4 + rr) * 16 + tt] = s[0][2 * rr][tt] + s[0][2 * rr + 1][tt];
        }
    }
}

extern "C" void kernel_launch(void* const* d_in, const int* in_sizes, int n_in,
                              void* d_out, int out_size) {
    const float* x       = (const float*)d_in[0];
    const float* weight  = (const float*)d_in[1];
    const int*   node_in = (const int*)d_in[2];
    const int*   top     = (const int*)d_in[3];
    const int*   bottom  = (const int*)d_in[4];
    const int*   left    = (const int*)d_in[5];
    const int*   right   = (const int*)d_in[6];
    float* out = (float*)d_out;
    (void)in_sizes; (void)n_in; (void)out_size;

    cudaFuncSetAttribute(k_mma, cudaFuncAttributeMaxDynamicSharedMemorySize, DYNSZ);
    k_prep<<<64 + 33, 256>>>(x, node_in, top, bottom, left, right);
    k_mma<<<(N_NODES + NPC - 1) / NPC, 256, DYNSZ>>>(weight);
    k_post<<<33, 256>>>(node_in, top, bottom, left, right, out);
}

// round 14
// speedup vs baseline: 1.9271x; 1.9271x over previous
#include <cuda_runtime.h>
#include <cstdint>

#define T_DIM   16
#define M_DIM   1024
#define K_DIM   4096
#define N_NODES 10000
#define N_IN    8000
#define N_B     100
#define NPC     64            // nodes per CTA -> 128 A-rows
#define NCHUNK  64            // K chunks of 64
#define DYNSZ   (64 * 1024)   // 2 bufs x (Ah 16KB + Al 16KB)

typedef unsigned long long u64;

// Scratch (zero-initialized; mark/compact idempotent across graph replays)
__device__ float g_f[N_NODES * 32];          // f[n][t][o]
__device__ int   g_mask[N_NODES];
__device__ int   g_list[N_NODES];
__device__ int   g_count;
__device__ uint4 g_xfrag[256 * 2 * 32];      // [ks][ntile][lane] = {b0h,b1h,b0l,b1l}

__device__ __forceinline__ uint32_t s2u(const void* p) {
    uint32_t a;
    asm("{ .reg .u64 t; cvta.to.shared.u64 t, %1; cvt.u32.u64 %0, t; }" : "=r"(a) : "l"(p));
    return a;
}
__device__ __forceinline__ uint32_t bf2(float hi, float lo) {   // bf16(hi)<<16 | bf16(lo)
    uint32_t d;
    asm("cvt.rn.bf16x2.f32 %0, %1, %2;" : "=r"(d) : "f"(hi), "f"(lo));
    return d;
}
__device__ __forceinline__ float hi16f(uint32_t w) { return __uint_as_float(w & 0xffff0000u); }
__device__ __forceinline__ float lo16f(uint32_t w) { return __uint_as_float(w << 16); }
__device__ __forceinline__ void sts32(uint32_t a, uint32_t v) {
    asm volatile("st.shared.b32 [%0], %1;" :: "r"(a), "r"(v) : "memory");
}
__device__ __forceinline__ void ldsm4(uint32_t& r0, uint32_t& r1, uint32_t& r2, uint32_t& r3,
                                      uint32_t addr) {
    asm volatile("ldmatrix.sync.aligned.m8n8.x4.shared.b16 {%0,%1,%2,%3}, [%4];"
                 : "=r"(r0), "=r"(r1), "=r"(r2), "=r"(r3) : "r"(addr));
}
__device__ __forceinline__ void mmabf(float d[4], uint32_t a0, uint32_t a1, uint32_t a2,
                                      uint32_t a3, uint32_t b0, uint32_t b1) {
    asm volatile("mma.sync.aligned.m16n8k16.row.col.f32.bf16.bf16.f32 "
                 "{%0,%1,%2,%3}, {%4,%5,%6,%7}, {%8,%9}, {%0,%1,%2,%3};"
                 : "+f"(d[0]), "+f"(d[1]), "+f"(d[2]), "+f"(d[3])
                 : "r"(a0), "r"(a1), "r"(a2), "r"(a3), "r"(b0), "r"(b1));
}
// swizzled byte offset inside a 128-rows x 128B A tile (16B-chunk XOR by row&7)
__device__ __forceinline__ uint32_t swz(uint32_t row, uint32_t bc) {
    return row * 128u + ((((bc >> 4) ^ (row & 7u)) << 4) | (bc & 15u));
}
__device__ __forceinline__ float xval(const float* __restrict__ x, int t, int i) {
    int m = i >> 2, j = i & 3;
    int p = (j == 0) ? 0 : ((j == 3) ? 1 : 2);   // [x0, x2, x2, x1]
    return x[(t * 3 + p) * M_DIM + m];
}

// ---- 1) prep: build x B-fragments (mma layout, bf16 hi/lo); mark+compact nodes ----
__global__ void k_prep(const float* __restrict__ x,
                       const int* __restrict__ node_in,
                       const int* __restrict__ top, const int* __restrict__ bottom,
                       const int* __restrict__ left, const int* __restrict__ right) {
    if (blockIdx.x < 64) {
        int id = blockIdx.x * 256 + threadIdx.x;   // 16384 = 256 ks * 2 ntile * 32 lanes
        int ks = id >> 6;
        int ln = id & 31;
        int t  = ((id >> 5) & 1) * 8 + (ln >> 2);  // n index = t
        int k0 = ks * 16 + 2 * (ln & 3);
        float v0 = xval(x, t, k0),     v1 = xval(x, t, k0 + 1);
        float v8 = xval(x, t, k0 + 8), v9 = xval(x, t, k0 + 9);
        uint32_t b0h = bf2(v1, v0);
        uint32_t b1h = bf2(v9, v8);
        uint32_t b0l = bf2(v1 - hi16f(b0h), v0 - lo16f(b0h));
        uint32_t b1l = bf2(v9 - hi16f(b1h), v8 - lo16f(b1h));
        g_xfrag[id] = make_uint4(b0h, b1h, b0l, b1l);
    } else {
        int idx = (blockIdx.x - 64) * 256 + threadIdx.x;
        int v = 0;
        if      (idx < N_IN)           v = node_in[idx];
        else if (idx < N_IN + 1*N_B)   v = top[idx - N_IN];
        else if (idx < N_IN + 2*N_B)   v = bottom[idx - N_IN - 1*N_B];
        else if (idx < N_IN + 3*N_B)   v = left[idx - N_IN - 2*N_B];
        else if (idx < N_IN + 4*N_B)   v = right[idx - N_IN - 3*N_B];
        if (v > 0 && atomicExch(&g_mask[v - 1], 1) == 0)
            g_list[atomicAdd(&g_count, 1)] = v - 1;
    }
}

// ---- 2) HMMA GEMM, 3-term bf16 split ----
// Staging remap (the R12 fix): thread (warp w, lane) stages nodes w+8r at
// float4-offset `lane` -> each LDG.128 warp-instr reads 512B contiguous of ONE
// node row (4 lines, optimal), and each STS has row constant across the warp
// (bank = perm(lane), conflict-free).
__global__ void __launch_bounds__(256)
k_mma(const float* __restrict__ weight) {
    extern __shared__ __align__(16) char dynraw[];
    const int count = g_count;
    const int base = blockIdx.x * NPC;
    if (base >= count) return;

    const int tid = threadIdx.x;
    const int nodesHere = (count - base < NPC) ? (count - base) : NPC;
    const int wrp = tid >> 5, lane = tid & 31;
    const uint32_t smem = s2u(dynraw);

    // staging pointers: node_local = wrp + 8r, float4 offset = lane (loop-invariant)
    const float4* wp[8];
    #pragma unroll
    for (int r = 0; r < 8; ++r) {
        int nl = wrp + 8 * r;
        int node = g_list[base + (nl < nodesHere ? nl : nodesHere - 1)];
        wp[r] = (const float4*)weight + (size_t)node * 2048 + lane;  // row = 2048 float4
    }

    float acc[2][4] = {{0.f,0.f,0.f,0.f},{0.f,0.f,0.f,0.f}};
    float4 rA[8], rB[8];
    #pragma unroll
    for (int r = 0; r < 8; ++r) rA[r] = __ldcs(wp[r]);               // chunk 0

    // ldmatrix lane geometry (constant over chunks)
    const int m      = lane >> 3;
    const uint32_t lrow = (uint32_t)(wrp * 16 + ((m & 1) << 3) + (lane & 7));
    const int kbofs  = m >> 1;

    #pragma unroll 1
    for (int c = 0; c < NCHUNK; ++c) {
        const int buf = c & 1;
        const int cn = (c + 1 < NCHUNK) ? c + 1 : c;
        #pragma unroll
        for (int r = 0; r < 8; ++r) rB[r] = __ldcs(wp[r] + cn * 32); // prefetch next

        // convert + store chunk c (rA): f = (w[i][0],w[i][1],w[i+1][0],w[i+1][1])
        const uint32_t aH = smem + (uint32_t)buf * 32768u;
        const uint32_t aL = aH + 16384u;
        const uint32_t bc = (uint32_t)lane * 4u;                     // col-pair bytes
        #pragma unroll
        for (int r = 0; r < 8; ++r) {
            float4 f = rA[r];
            uint32_t row0 = 2u * (uint32_t)(wrp + 8 * r);
            uint32_t h0 = bf2(f.z, f.x);
            uint32_t l0 = bf2(f.z - hi16f(h0), f.x - lo16f(h0));
            uint32_t h1 = bf2(f.w, f.y);
            uint32_t l1 = bf2(f.w - hi16f(h1), f.y - lo16f(h1));
            uint32_t o0 = swz(row0, bc), o1 = swz(row0 + 1, bc);
            sts32(aH + o0, h0); sts32(aL + o0, l0);
            sts32(aH + o1, h1); sts32(aL + o1, l1);
        }
        __syncthreads();     // single sync/chunk: 2 buffers make this hazard-free

        // MMA: warp owns rows 16*wrp..16*wrp+15
        #pragma unroll
        for (int ks = 0; ks < 4; ++ks) {
            uint32_t adr = aH + swz(lrow, (uint32_t)((2 * ks + kbofs) << 4));
            uint32_t a0, a1, a2, a3, q0, q1, q2, q3;
            ldsm4(a0, a1, a2, a3, adr);              // Ah fragment
            ldsm4(q0, q1, q2, q3, adr + 16384u);     // Al fragment
            #pragma unroll
            for (int nt = 0; nt < 2; ++nt) {
                uint4 bf = g_xfrag[(c * 4 + ks) * 64 + nt * 32 + lane];
                mmabf(acc[nt], a0, a1, a2, a3, bf.x, bf.y);   // Ah*Bh
                mmabf(acc[nt], a0, a1, a2, a3, bf.z, bf.w);   // Ah*Bl
                mmabf(acc[nt], q0, q1, q2, q3, bf.x, bf.y);   // Al*Bh
            }
        }
        #pragma unroll
        for (int r = 0; r < 8; ++r) rA[r] = rB[r];
    }

    // epilogue: D fragment -> g_f.  d0,d1: row g, cols 2t2,2t2+1; d2,d3: row g+8
    const int g = lane >> 2, t2 = lane & 3;
    #pragma unroll
    for (int half = 0; half < 2; ++half) {
        int row = wrp * 16 + g + half * 8;
        int rnl = row >> 1, o = row & 1;
        int nd = g_list[base + (rnl < nodesHere ? rnl : nodesHere - 1)];
        #pragma unroll
        for (int nt = 0; nt < 2; ++nt) {
            int t = nt * 8 + 2 * t2;
            g_f[nd * 32 + 2 * t + o]       = acc[nt][half * 2 + 0];
            g_f[nd * 32 + 2 * (t + 1) + o] = acc[nt][half * 2 + 1];
        }
    }
}

// ---- 3) epilogue: gather (blocks 0..249, 1 float4/thread) + boundary (block 250) ----
__global__ void k_post(const int* __restrict__ node_in,
                       const int* __restrict__ top, const int* __restrict__ bottom,
                       const int* __restrict__ left, const int* __restrict__ right,
                       float* __restrict__ out) {
    if (blockIdx.x < 250) {
        int e = blockIdx.x * 256 + threadIdx.x;     // covers N_IN*8 = 64000 float4
        int k = e >> 3, r = e & 7;
        ((float4*)out)[e] = ((const float4*)g_f)[(size_t)(node_in[k] - 1) * 8 + r];
    } else {
        __shared__ float s[4][4][16];
        const int tid = threadIdx.x;
        const int ch = tid >> 6, rt = tid & 63, r = rt >> 4, t = rt & 15;
        const int* arr = (r == 0) ? top : (r == 1) ? bottom : (r == 2) ? left : right;
        const int o = (r < 2) ? 1 : 0;
        float sum = 0.0f;
        #pragma unroll
        for (int b = 25 * ch; b < 25 * ch + 25; ++b)
            sum += g_f[(arr[b] - 1) * 32 + t * 2 + o];
        s[ch][r][t] = sum;
        __syncthreads();
        float* ob = out + N_IN * 32;
        if (tid < 64) {
            float v = s[0][r][t] + s[1][r][t] + s[2][r][t] + s[3][r][t];
            s[0][r][t] = v;
            ob[r * 16 + t] = v;
        }
        __syncthreads();
        if (tid < 32) {
            int rr = tid >> 4, tt = tid & 15;        // 0: top+bottom, 1: left+right
            ob[(4 + rr) * 16 + tt] = s[0][2 * rr][tt] + s[0][2 * rr + 1][tt];
        }
    }
}

extern "C" void kernel_launch(void* const* d_in, const int* in_sizes, int n_in,
                              void* d_out, int out_size) {
    const float* x       = (const float*)d_in[0];
    const float* weight  = (const float*)d_in[1];
    const int*   node_in = (const int*)d_in[2];
    const int*   top     = (const int*)d_in[3];
    const int*   bottom  = (const int*)d_in[4];
    const int*   left    = (const int*)d_in[5];
    const int*   right   = (const int*)d_in[6];
    float* out = (float*)d_out;
    (void)in_sizes; (void)n_in; (void)out_size;

    cudaFuncSetAttribute(k_mma, cudaFuncAttributeMaxDynamicSharedMemorySize, DYNSZ);
    k_prep<<<64 + 33, 256>>>(x, node_in, top, bottom, left, right);
    k_mma<<<(N_NODES + NPC - 1) / NPC, 256, DYNSZ>>>(weight);
    k_post<<<251, 256>>>(node_in, top, bottom, left, right, out);
}

// round 15
// speedup vs baseline: 2.4827x; 1.2883x over previous
#include <cuda_runtime.h>
#include <cstdint>

#define T_DIM   16
#define M_DIM   1024
#define K_DIM   4096
#define N_NODES 10000
#define N_IN    8000
#define N_B     100
#define NPC     32            // nodes per CTA -> 64 A-rows, 4 warps
#define NCHUNK  64            // K chunks of 64
#define DYNSZ   (32 * 1024)   // 2 bufs x (Ah 8KB + Al 8KB)

typedef unsigned long long u64;

// Scratch (zero-initialized; mark/compact idempotent across graph replays)
__device__ float g_f[N_NODES * 32];          // f[n][t][o]
__device__ int   g_mask[N_NODES];
__device__ int   g_list[N_NODES];
__device__ int   g_count;
__device__ uint4 g_xfrag[256 * 2 * 32];      // [ks][ntile][lane] = {b0h,b1h,b0l,b1l}

__device__ __forceinline__ uint32_t s2u(const void* p) {
    uint32_t a;
    asm("{ .reg .u64 t; cvta.to.shared.u64 t, %1; cvt.u32.u64 %0, t; }" : "=r"(a) : "l"(p));
    return a;
}
__device__ __forceinline__ uint32_t bf2(float hi, float lo) {   // bf16(hi)<<16 | bf16(lo)
    uint32_t d;
    asm("cvt.rn.bf16x2.f32 %0, %1, %2;" : "=r"(d) : "f"(hi), "f"(lo));
    return d;
}
__device__ __forceinline__ float hi16f(uint32_t w) { return __uint_as_float(w & 0xffff0000u); }
__device__ __forceinline__ float lo16f(uint32_t w) { return __uint_as_float(w << 16); }
__device__ __forceinline__ void sts32(uint32_t a, uint32_t v) {
    asm volatile("st.shared.b32 [%0], %1;" :: "r"(a), "r"(v) : "memory");
}
__device__ __forceinline__ void ldsm4(uint32_t& r0, uint32_t& r1, uint32_t& r2, uint32_t& r3,
                                      uint32_t addr) {
    asm volatile("ldmatrix.sync.aligned.m8n8.x4.shared.b16 {%0,%1,%2,%3}, [%4];"
                 : "=r"(r0), "=r"(r1), "=r"(r2), "=r"(r3) : "r"(addr));
}
__device__ __forceinline__ void mmabf(float d[4], uint32_t a0, uint32_t a1, uint32_t a2,
                                      uint32_t a3, uint32_t b0, uint32_t b1) {
    asm volatile("mma.sync.aligned.m16n8k16.row.col.f32.bf16.bf16.f32 "
                 "{%0,%1,%2,%3}, {%4,%5,%6,%7}, {%8,%9}, {%0,%1,%2,%3};"
                 : "+f"(d[0]), "+f"(d[1]), "+f"(d[2]), "+f"(d[3])
                 : "r"(a0), "r"(a1), "r"(a2), "r"(a3), "r"(b0), "r"(b1));
}
// swizzled byte offset inside a 64-rows x 128B A tile (16B-chunk XOR by row&7)
__device__ __forceinline__ uint32_t swz(uint32_t row, uint32_t bc) {
    return row * 128u + ((((bc >> 4) ^ (row & 7u)) << 4) | (bc & 15u));
}
__device__ __forceinline__ float xval(const float* __restrict__ x, int t, int i) {
    int m = i >> 2, j = i & 3;
    int p = (j == 0) ? 0 : ((j == 3) ? 1 : 2);   // [x0, x2, x2, x1]
    return x[(t * 3 + p) * M_DIM + m];
}

// ---- 1) prep: build x B-fragments (mma layout, bf16 hi/lo); mark+compact nodes ----
__global__ void k_prep(const float* __restrict__ x,
                       const int* __restrict__ node_in,
                       const int* __restrict__ top, const int* __restrict__ bottom,
                       const int* __restrict__ left, const int* __restrict__ right) {
    if (blockIdx.x < 64) {
        int id = blockIdx.x * 256 + threadIdx.x;   // 16384 = 256 ks * 2 ntile * 32 lanes
        int ks = id >> 6;
        int ln = id & 31;
        int t  = ((id >> 5) & 1) * 8 + (ln >> 2);  // n index = t
        int k0 = ks * 16 + 2 * (ln & 3);
        float v0 = xval(x, t, k0),     v1 = xval(x, t, k0 + 1);
        float v8 = xval(x, t, k0 + 8), v9 = xval(x, t, k0 + 9);
        uint32_t b0h = bf2(v1, v0);
        uint32_t b1h = bf2(v9, v8);
        uint32_t b0l = bf2(v1 - hi16f(b0h), v0 - lo16f(b0h));
        uint32_t b1l = bf2(v9 - hi16f(b1h), v8 - lo16f(b1h));
        g_xfrag[id] = make_uint4(b0h, b1h, b0l, b1l);
    } else {
        int idx = (blockIdx.x - 64) * 256 + threadIdx.x;
        int v = 0;
        if      (idx < N_IN)           v = node_in[idx];
        else if (idx < N_IN + 1*N_B)   v = top[idx - N_IN];
        else if (idx < N_IN + 2*N_B)   v = bottom[idx - N_IN - 1*N_B];
        else if (idx < N_IN + 3*N_B)   v = left[idx - N_IN - 2*N_B];
        else if (idx < N_IN + 4*N_B)   v = right[idx - N_IN - 3*N_B];
        if (v > 0 && atomicExch(&g_mask[v - 1], 1) == 0)
            g_list[atomicAdd(&g_count, 1)] = v - 1;
    }
}

// ---- 2) HMMA GEMM, 3-term bf16 split ----
// 32 nodes/CTA = 64 A-rows, 4 warps (warp w owns rows 16w..16w+15).
// Staging: thread (w, lane) stages nodes w+4r (r=0..7) at float4-offset lane:
// each LDG.128 warp-instr reads 512B contiguous of ONE node row; each STS has
// row constant across the warp (bank = perm(lane), conflict-free).
// Weight AND xfrag loads double-buffered in registers (distance-1 prefetch).
__global__ void __launch_bounds__(128)
k_mma(const float* __restrict__ weight) {
    extern __shared__ __align__(16) char dynraw[];
    const int count = g_count;
    const int base = blockIdx.x * NPC;
    if (base >= count) return;

    const int tid = threadIdx.x;
    const int nodesHere = (count - base < NPC) ? (count - base) : NPC;
    const int wrp = tid >> 5, lane = tid & 31;
    const uint32_t smem = s2u(dynraw);

    // staging pointers: node_local = wrp + 4r, float4 offset = lane
    const float4* wp[8];
    #pragma unroll
    for (int r = 0; r < 8; ++r) {
        int nl = wrp + 4 * r;
        int node = g_list[base + (nl < nodesHere ? nl : nodesHere - 1)];
        wp[r] = (const float4*)weight + (size_t)node * 2048 + lane;  // row = 2048 float4
    }

    float acc[2][4] = {{0.f,0.f,0.f,0.f},{0.f,0.f,0.f,0.f}};
    float4 rA[8], rB[8];
    uint4  xfA[8], xfB[8];
    #pragma unroll
    for (int r = 0; r < 8; ++r) rA[r] = __ldcs(wp[r]);               // weights chunk 0
    #pragma unroll
    for (int q = 0; q < 8; ++q) xfA[q] = g_xfrag[q * 32 + lane];     // xfrag chunk 0

    // ldmatrix lane geometry (constant over chunks)
    const int m      = lane >> 3;
    const uint32_t lrow = (uint32_t)(wrp * 16 + ((m & 1) << 3) + (lane & 7));
    const int kbofs  = m >> 1;

    #pragma unroll 1
    for (int c = 0; c < NCHUNK; ++c) {
        const int buf = c & 1;
        const int cn = (c + 1 < NCHUNK) ? c + 1 : c;
        #pragma unroll
        for (int r = 0; r < 8; ++r) rB[r] = __ldcs(wp[r] + cn * 32); // weights c+1
        #pragma unroll
        for (int q = 0; q < 8; ++q) xfB[q] = g_xfrag[cn * 256 + q * 32 + lane]; // xfrag c+1

        // convert + store chunk c (rA): f = (w[i][0],w[i][1],w[i+1][0],w[i+1][1])
        const uint32_t aH = smem + (uint32_t)buf * 16384u;
        const uint32_t aL = aH + 8192u;
        const uint32_t bc = (uint32_t)lane * 4u;                     // col-pair bytes
        #pragma unroll
        for (int r = 0; r < 8; ++r) {
            float4 f = rA[r];
            uint32_t row0 = 2u * (uint32_t)(wrp + 4 * r);
            uint32_t h0 = bf2(f.z, f.x);
            uint32_t l0 = bf2(f.z - hi16f(h0), f.x - lo16f(h0));
            uint32_t h1 = bf2(f.w, f.y);
            uint32_t l1 = bf2(f.w - hi16f(h1), f.y - lo16f(h1));
            uint32_t o0 = swz(row0, bc), o1 = swz(row0 + 1, bc);
            sts32(aH + o0, h0); sts32(aL + o0, l0);
            sts32(aH + o1, h1); sts32(aL + o1, l1);
        }
        __syncthreads();     // single sync/chunk: 2 buffers make this hazard-free

        // MMA: warp owns rows 16*wrp..16*wrp+15; xfrag from registers
        #pragma unroll
        for (int ks = 0; ks < 4; ++ks) {
            uint32_t adr = aH + swz(lrow, (uint32_t)((2 * ks + kbofs) << 4));
            uint32_t a0, a1, a2, a3, q0, q1, q2, q3;
            ldsm4(a0, a1, a2, a3, adr);              // Ah fragment
            ldsm4(q0, q1, q2, q3, adr + 8192u);      // Al fragment
            #pragma unroll
            for (int nt = 0; nt < 2; ++nt) {
                uint4 bf = xfA[ks * 2 + nt];
                mmabf(acc[nt], a0, a1, a2, a3, bf.x, bf.y);   // Ah*Bh
                mmabf(acc[nt], a0, a1, a2, a3, bf.z, bf.w);   // Ah*Bl
                mmabf(acc[nt], q0, q1, q2, q3, bf.x, bf.y);   // Al*Bh
            }
        }
        #pragma unroll
        for (int r = 0; r < 8; ++r) rA[r] = rB[r];
        #pragma unroll
        for (int q = 0; q < 8; ++q) xfA[q] = xfB[q];
    }

    // epilogue: D fragment -> g_f.  d0,d1: row g, cols 2t2,2t2+1; d2,d3: row g+8
    const int g = lane >> 2, t2 = lane & 3;
    #pragma unroll
    for (int half = 0; half < 2; ++half) {
        int row = wrp * 16 + g + half * 8;
        int rnl = row >> 1, o = row & 1;
        int nd = g_list[base + (rnl < nodesHere ? rnl : nodesHere - 1)];
        #pragma unroll
        for (int nt = 0; nt < 2; ++nt) {
            int t = nt * 8 + 2 * t2;
            g_f[nd * 32 + 2 * t + o]       = acc[nt][half * 2 + 0];
            g_f[nd * 32 + 2 * (t + 1) + o] = acc[nt][half * 2 + 1];
        }
    }
}

// ---- 3) epilogue: gather (blocks 0..249, 1 float4/thread) + boundary (block 250) ----
__global__ void k_post(const int* __restrict__ node_in,
                       const int* __restrict__ top, const int* __restrict__ bottom,
                       const int* __restrict__ left, const int* __restrict__ right,
                       float* __restrict__ out) {
    if (blockIdx.x < 250) {
        int e = blockIdx.x * 256 + threadIdx.x;     // covers N_IN*8 = 64000 float4
        int k = e >> 3, r = e & 7;
        ((float4*)out)[e] = ((const float4*)g_f)[(size_t)(node_in[k] - 1) * 8 + r];
    } else {
        __shared__ float s[4][4][16];
        const int tid = threadIdx.x;
        const int ch = tid >> 6, rt = tid & 63, r = rt >> 4, t = rt & 15;
        const int* arr = (r == 0) ? top : (r == 1) ? bottom : (r == 2) ? left : right;
        const int o = (r < 2) ? 1 : 0;
        float sum = 0.0f;
        #pragma unroll
        for (int b = 25 * ch; b < 25 * ch + 25; ++b)
            sum += g_f[(arr[b] - 1) * 32 + t * 2 + o];
        s[ch][r][t] = sum;
        __syncthreads();
        float* ob = out + N_IN * 32;
        if (tid < 64) {
            float v = s[0][r][t] + s[1][r][t] + s[2][r][t] + s[3][r][t];
            s[0][r][t] = v;
            ob[r * 16 + t] = v;
        }
        __syncthreads();
        if (tid < 32) {
            int rr = tid >> 4, tt = tid & 15;        // 0: top+bottom, 1: left+right
            ob[(4 + rr) * 16 + tt] = s[0][2 * rr][tt] + s[0][2 * rr + 1][tt];
        }
    }
}

extern "C" void kernel_launch(void* const* d_in, const int* in_sizes, int n_in,
                              void* d_out, int out_size) {
    const float* x       = (const float*)d_in[0];
    const float* weight  = (const float*)d_in[1];
    const int*   node_in = (const int*)d_in[2];
    const int*   top     = (const int*)d_in[3];
    const int*   bottom  = (const int*)d_in[4];
    const int*   left    = (const int*)d_in[5];
    const int*   right   = (const int*)d_in[6];
    float* out = (float*)d_out;
    (void)in_sizes; (void)n_in; (void)out_size;

    cudaFuncSetAttribute(k_mma, cudaFuncAttributeMaxDynamicSharedMemorySize, DYNSZ);
    k_prep<<<64 + 33, 256>>>(x, node_in, top, bottom, left, right);
    k_mma<<<(N_NODES + NPC - 1) / NPC, 128, DYNSZ>>>(weight);
    k_post<<<251, 256>>>(node_in, top, bottom, left, right, out);
}

// round 16
// speedup vs baseline: 2.5585x; 1.0306x over previous
#include <cuda_runtime.h>
#include <cstdint>

#define T_DIM   16
#define M_DIM   1024
#define K_DIM   4096
#define N_NODES 10000
#define N_IN    8000
#define N_B     100
#define NPC     32            // nodes per CTA -> 64 A-rows, 4 warps
#define NCHUNK  64            // K chunks of 64
#define DYNSZ   (32 * 1024)   // 2 bufs x (Ah 8KB + Al 8KB)

typedef unsigned long long u64;

// Scratch (zero-initialized; mark/compact idempotent across graph replays)
__device__ float g_f[N_NODES * 32];          // f[n][t][o]
__device__ int   g_mask[N_NODES];
__device__ int   g_list[N_NODES];
__device__ int   g_count;
__device__ uint4 g_xfrag[256 * 2 * 32];      // [ks][ntile][lane] = {b0h,b1h,b0l,b1l}

__device__ __forceinline__ uint32_t s2u(const void* p) {
    uint32_t a;
    asm("{ .reg .u64 t; cvta.to.shared.u64 t, %1; cvt.u32.u64 %0, t; }" : "=r"(a) : "l"(p));
    return a;
}
__device__ __forceinline__ uint32_t bf2(float hi, float lo) {   // bf16(hi)<<16 | bf16(lo)
    uint32_t d;
    asm("cvt.rn.bf16x2.f32 %0, %1, %2;" : "=r"(d) : "f"(hi), "f"(lo));
    return d;
}
__device__ __forceinline__ float hi16f(uint32_t w) { return __uint_as_float(w & 0xffff0000u); }
__device__ __forceinline__ float lo16f(uint32_t w) { return __uint_as_float(w << 16); }
__device__ __forceinline__ void sts64(uint32_t a, uint32_t v0, uint32_t v1) {
    asm volatile("st.shared.v2.b32 [%0], {%1,%2};" :: "r"(a), "r"(v0), "r"(v1) : "memory");
}
__device__ __forceinline__ void ldsm4(uint32_t& r0, uint32_t& r1, uint32_t& r2, uint32_t& r3,
                                      uint32_t addr) {
    asm volatile("ldmatrix.sync.aligned.m8n8.x4.shared.b16 {%0,%1,%2,%3}, [%4];"
                 : "=r"(r0), "=r"(r1), "=r"(r2), "=r"(r3) : "r"(addr));
}
__device__ __forceinline__ void mmabf(float d[4], uint32_t a0, uint32_t a1, uint32_t a2,
                                      uint32_t a3, uint32_t b0, uint32_t b1) {
    asm volatile("mma.sync.aligned.m16n8k16.row.col.f32.bf16.bf16.f32 "
                 "{%0,%1,%2,%3}, {%4,%5,%6,%7}, {%8,%9}, {%0,%1,%2,%3};"
                 : "+f"(d[0]), "+f"(d[1]), "+f"(d[2]), "+f"(d[3])
                 : "r"(a0), "r"(a1), "r"(a2), "r"(a3), "r"(b0), "r"(b1));
}
// swizzled byte offset inside a 64-rows x 128B A tile (16B-chunk XOR by row&7)
__device__ __forceinline__ uint32_t swz(uint32_t row, uint32_t bc) {
    return row * 128u + ((((bc >> 4) ^ (row & 7u)) << 4) | (bc & 15u));
}
__device__ __forceinline__ float xval(const float* __restrict__ x, int t, int i) {
    int m = i >> 2, j = i & 3;
    int p = (j == 0) ? 0 : ((j == 3) ? 1 : 2);   // [x0, x2, x2, x1]
    return x[(t * 3 + p) * M_DIM + m];
}

// ---- 1) prep: build x B-fragments (mma layout, bf16 hi/lo); mark+compact nodes ----
__global__ void k_prep(const float* __restrict__ x,
                       const int* __restrict__ node_in,
                       const int* __restrict__ top, const int* __restrict__ bottom,
                       const int* __restrict__ left, const int* __restrict__ right) {
    if (blockIdx.x < 64) {
        int id = blockIdx.x * 256 + threadIdx.x;   // 16384 = 256 ks * 2 ntile * 32 lanes
        int ks = id >> 6;
        int ln = id & 31;
        int t  = ((id >> 5) & 1) * 8 + (ln >> 2);  // n index = t
        int k0 = ks * 16 + 2 * (ln & 3);
        float v0 = xval(x, t, k0),     v1 = xval(x, t, k0 + 1);
        float v8 = xval(x, t, k0 + 8), v9 = xval(x, t, k0 + 9);
        uint32_t b0h = bf2(v1, v0);
        uint32_t b1h = bf2(v9, v8);
        uint32_t b0l = bf2(v1 - hi16f(b0h), v0 - lo16f(b0h));
        uint32_t b1l = bf2(v9 - hi16f(b1h), v8 - lo16f(b1h));
        g_xfrag[id] = make_uint4(b0h, b1h, b0l, b1l);
    } else {
        int idx = (blockIdx.x - 64) * 256 + threadIdx.x;
        int v = 0;
        if      (idx < N_IN)           v = node_in[idx];
        else if (idx < N_IN + 1*N_B)   v = top[idx - N_IN];
        else if (idx < N_IN + 2*N_B)   v = bottom[idx - N_IN - 1*N_B];
        else if (idx < N_IN + 3*N_B)   v = left[idx - N_IN - 2*N_B];
        else if (idx < N_IN + 4*N_B)   v = right[idx - N_IN - 3*N_B];
        if (v > 0 && atomicExch(&g_mask[v - 1], 1) == 0)
            g_list[atomicAdd(&g_count, 1)] = v - 1;
    }
}

// ---- 2) HMMA GEMM, 3-term bf16 split ----
// Lane = (s=lane>>4, l16=lane&15). Thread stages 4 nodes (w + 8r + 4s) with 2
// consecutive float4 each (32B contiguous LDG per node), producing 8B-contiguous
// rows -> STS.64, conflict-free. All swizzle addresses precomputed; chunk loop
// unrolled x2 with A/B role swap (no register copies).
#define CHUNK_STEP(C_, CUR, NXT, XCUR, XNXT)                                     \
{                                                                                \
    const int cn_ = ((C_) + 1) & 63;                                             \
    _Pragma("unroll")                                                            \
    for (int r = 0; r < 4; ++r) {                                                \
        NXT[2*r]   = __ldcs(wq[r] + cn_ * 32);                                   \
        NXT[2*r+1] = __ldcs(wq[r] + cn_ * 32 + 1);                               \
    }                                                                            \
    _Pragma("unroll")                                                            \
    for (int q = 0; q < 8; ++q) XNXT[q] = xfp[cn_ * 256 + q * 32];               \
    const uint32_t aH_ = smem + (uint32_t)(((C_) & 1) * 16384);                  \
    _Pragma("unroll")                                                            \
    for (int r = 0; r < 4; ++r) {                                                \
        float4 A = CUR[2*r], B = CUR[2*r+1];                                     \
        uint32_t h0a = bf2(A.z, A.x), h0b = bf2(B.z, B.x);                       \
        uint32_t l0a = bf2(A.z - hi16f(h0a), A.x - lo16f(h0a));                  \
        uint32_t l0b = bf2(B.z - hi16f(h0b), B.x - lo16f(h0b));                  \
        uint32_t h1a = bf2(A.w, A.y), h1b = bf2(B.w, B.y);                       \
        uint32_t l1a = bf2(A.w - hi16f(h1a), A.y - lo16f(h1a));                  \
        uint32_t l1b = bf2(B.w - hi16f(h1b), B.y - lo16f(h1b));                  \
        sts64(aH_ + adr0[r], h0a, h0b);                                          \
        sts64(aH_ + 8192u + adr0[r], l0a, l0b);                                  \
        sts64(aH_ + adr1[r], h1a, h1b);                                          \
        sts64(aH_ + 8192u + adr1[r], l1a, l1b);                                  \
    }                                                                            \
    __syncthreads();                                                             \
    _Pragma("unroll")                                                            \
    for (int ks = 0; ks < 4; ++ks) {                                             \
        uint32_t adr = aH_ + lds_adr[ks];                                        \
        uint32_t a0, a1, a2, a3, q0, q1, q2, q3;                                 \
        ldsm4(a0, a1, a2, a3, adr);                                              \
        ldsm4(q0, q1, q2, q3, adr + 8192u);                                      \
        _Pragma("unroll")                                                        \
        for (int nt = 0; nt < 2; ++nt) {                                         \
            uint4 bf = XCUR[ks * 2 + nt];                                        \
            mmabf(acc[nt], a0, a1, a2, a3, bf.x, bf.y);                          \
            mmabf(acc[nt], a0, a1, a2, a3, bf.z, bf.w);                          \
            mmabf(acc[nt], q0, q1, q2, q3, bf.x, bf.y);                          \
        }                                                                        \
    }                                                                            \
}

__global__ void __launch_bounds__(128)
k_mma(const float* __restrict__ weight) {
    extern __shared__ __align__(16) char dynraw[];
    const int count = g_count;
    const int base = blockIdx.x * NPC;
    if (base >= count) return;

    const int tid = threadIdx.x;
    const int nodesHere = (count - base < NPC) ? (count - base) : NPC;
    const int wrp = tid >> 5, lane = tid & 31;
    const int l16 = lane & 15, s = lane >> 4;
    const uint32_t smem = s2u(dynraw);

    // node pointers + precomputed swizzled STS addresses (loop-invariant)
    const float4* wq[4];
    uint32_t adr0[4], adr1[4];
    #pragma unroll
    for (int r = 0; r < 4; ++r) {
        int nl = wrp + 8 * r + 4 * s;
        int node = g_list[base + (nl < nodesHere ? nl : nodesHere - 1)];
        wq[r] = (const float4*)weight + (size_t)node * 2048 + 2 * l16;
        uint32_t row0 = 2u * (uint32_t)nl;
        adr0[r] = swz(row0,     (uint32_t)(8 * l16));
        adr1[r] = swz(row0 + 1, (uint32_t)(8 * l16));
    }
    // ldmatrix addresses (loop-invariant)
    const int m = lane >> 3;
    const uint32_t lrow = (uint32_t)(wrp * 16 + ((m & 1) << 3) + (lane & 7));
    const int kbofs = m >> 1;
    uint32_t lds_adr[4];
    #pragma unroll
    for (int ks = 0; ks < 4; ++ks)
        lds_adr[ks] = swz(lrow, (uint32_t)((2 * ks + kbofs) << 4));
    const uint4* __restrict__ xfp = g_xfrag + lane;

    float acc[2][4] = {{0.f,0.f,0.f,0.f},{0.f,0.f,0.f,0.f}};
    float4 rA[8], rB[8];
    uint4  xfA[8], xfB[8];
    #pragma unroll
    for (int r = 0; r < 4; ++r) {                    // chunk 0 weights
        rA[2*r]   = __ldcs(wq[r]);
        rA[2*r+1] = __ldcs(wq[r] + 1);
    }
    #pragma unroll
    for (int q = 0; q < 8; ++q) xfA[q] = xfp[q * 32];   // chunk 0 xfrag

    #pragma unroll 1
    for (int c = 0; c < NCHUNK; c += 2) {
        CHUNK_STEP(c,     rA, rB, xfA, xfB)
        CHUNK_STEP(c + 1, rB, rA, xfB, xfA)
    }

    // epilogue: D fragment -> g_f.  d0,d1: row g, cols 2t2,2t2+1; d2,d3: row g+8
    const int g = lane >> 2, t2 = lane & 3;
    #pragma unroll
    for (int half = 0; half < 2; ++half) {
        int row = wrp * 16 + g + half * 8;
        int rnl = row >> 1, o = row & 1;
        int nd = g_list[base + (rnl < nodesHere ? rnl : nodesHere - 1)];
        #pragma unroll
        for (int nt = 0; nt < 2; ++nt) {
            int t = nt * 8 + 2 * t2;
            g_f[nd * 32 + 2 * t + o]       = acc[nt][half * 2 + 0];
            g_f[nd * 32 + 2 * (t + 1) + o] = acc[nt][half * 2 + 1];
        }
    }
}

// ---- 3) epilogue: ILP-4 gather (blocks 0..63) + boundary sums (block 64) ----
__global__ void k_post(const int* __restrict__ node_in,
                       const int* __restrict__ top, const int* __restrict__ bottom,
                       const int* __restrict__ left, const int* __restrict__ right,
                       float* __restrict__ out) {
    if (blockIdx.x < 64) {
        int j = blockIdx.x * 256 + threadIdx.x;
        #pragma unroll
        for (int i = 0; i < 4; ++i) {
            int e = j + i * 16384;                   // N_IN*8 = 64000 float4
            if (e < N_IN * 8) {
                int k = e >> 3, r = e & 7;
                ((float4*)out)[e] = ((const float4*)g_f)[(size_t)(node_in[k] - 1) * 8 + r];
            }
        }
    } else {
        __shared__ float ssum[4][4][16];
        const int tid = threadIdx.x;
        const int ch = tid >> 6, rt = tid & 63, r = rt >> 4, t = rt & 15;
        const int* arr = (r == 0) ? top : (r == 1) ? bottom : (r == 2) ? left : right;
        const int o = (r < 2) ? 1 : 0;
        float sum = 0.0f;
        #pragma unroll
        for (int b = 25 * ch; b < 25 * ch + 25; ++b)
            sum += g_f[(arr[b] - 1) * 32 + t * 2 + o];
        ssum[ch][r][t] = sum;
        __syncthreads();
        float* ob = out + N_IN * 32;
        if (tid < 64) {
            float v = ssum[0][r][t] + ssum[1][r][t] + ssum[2][r][t] + ssum[3][r][t];
            ssum[0][r][t] = v;
            ob[r * 16 + t] = v;
        }
        __syncthreads();
        if (tid < 32) {
            int rr = tid >> 4, tt = tid & 15;        // 0: top+bottom, 1: left+right
            ob[(4 + rr) * 16 + tt] = ssum[0][2 * rr][tt] + ssum[0][2 * rr + 1][tt];
        }
    }
}

extern "C" void kernel_launch(void* const* d_in, const int* in_sizes, int n_in,
                              void* d_out, int out_size) {
    const float* x       = (const float*)d_in[0];
    const float* weight  = (const float*)d_in[1];
    const int*   node_in = (const int*)d_in[2];
    const int*   top     = (const int*)d_in[3];
    const int*   bottom  = (const int*)d_in[4];
    const int*   left    = (const int*)d_in[5];
    const int*   right   = (const int*)d_in[6];
    float* out = (float*)d_out;
    (void)in_sizes; (void)n_in; (void)out_size;

    cudaFuncSetAttribute(k_mma, cudaFuncAttributeMaxDynamicSharedMemorySize, DYNSZ);
    k_prep<<<64 + 33, 256>>>(x, node_in, top, bottom, left, right);
    k_mma<<<(N_NODES + NPC - 1) / NPC, 128, DYNSZ>>>(weight);
    k_post<<<65, 256>>>(node_in, top, bottom, left, right, out);
}

// round 17
// speedup vs baseline: 2.7115x; 1.0598x over previous
#include <cuda_runtime.h>
#include <cstdint>

#define T_DIM   16
#define M_DIM   1024
#define K_DIM   4096
#define N_NODES 10000
#define N_IN    8000
#define N_B     100
#define NPC     32            // nodes per CTA; 4 warps x 8 nodes, warp-private tiles
#define NCHUNK  64            // K chunks of 64
#define DYNSZ   (32 * 1024)   // 4 warps x 2 bufs x (hi 2KB + lo 2KB)

typedef unsigned long long u64;

// Scratch (zero-initialized; mark/compact idempotent across graph replays)
__device__ float g_f[N_NODES * 32];          // f[n][t][o]
__device__ int   g_mask[N_NODES];
__device__ int   g_list[N_NODES];
__device__ int   g_count;
__device__ uint4 g_xfrag[256 * 2 * 32];      // [ks][ntile][lane] = {b0h,b1h,b0l,b1l}

__device__ __forceinline__ uint32_t s2u(const void* p) {
    uint32_t a;
    asm("{ .reg .u64 t; cvta.to.shared.u64 t, %1; cvt.u32.u64 %0, t; }" : "=r"(a) : "l"(p));
    return a;
}
__device__ __forceinline__ uint32_t bf2(float hi, float lo) {   // bf16(hi)<<16 | bf16(lo)
    uint32_t d;
    asm("cvt.rn.bf16x2.f32 %0, %1, %2;" : "=r"(d) : "f"(hi), "f"(lo));
    return d;
}
__device__ __forceinline__ float hi16f(uint32_t w) { return __uint_as_float(w & 0xffff0000u); }
__device__ __forceinline__ float lo16f(uint32_t w) { return __uint_as_float(w << 16); }
__device__ __forceinline__ void sts32(uint32_t a, uint32_t v) {
    asm volatile("st.shared.b32 [%0], %1;" :: "r"(a), "r"(v) : "memory");
}
__device__ __forceinline__ void ldsm4(uint32_t& r0, uint32_t& r1, uint32_t& r2, uint32_t& r3,
                                      uint32_t addr) {
    asm volatile("ldmatrix.sync.aligned.m8n8.x4.shared.b16 {%0,%1,%2,%3}, [%4];"
                 : "=r"(r0), "=r"(r1), "=r"(r2), "=r"(r3) : "r"(addr));
}
__device__ __forceinline__ void mmabf(float d[4], uint32_t a0, uint32_t a1, uint32_t a2,
                                      uint32_t a3, uint32_t b0, uint32_t b1) {
    asm volatile("mma.sync.aligned.m16n8k16.row.col.f32.bf16.bf16.f32 "
                 "{%0,%1,%2,%3}, {%4,%5,%6,%7}, {%8,%9}, {%0,%1,%2,%3};"
                 : "+f"(d[0]), "+f"(d[1]), "+f"(d[2]), "+f"(d[3])
                 : "r"(a0), "r"(a1), "r"(a2), "r"(a3), "r"(b0), "r"(b1));
}
// swizzled byte offset inside a 16-rows x 128B tile (16B-chunk XOR by row&7)
__device__ __forceinline__ uint32_t swz(uint32_t row, uint32_t bc) {
    return row * 128u + ((((bc >> 4) ^ (row & 7u)) << 4) | (bc & 15u));
}
__device__ __forceinline__ float xval(const float* __restrict__ x, int t, int i) {
    int m = i >> 2, j = i & 3;
    int p = (j == 0) ? 0 : ((j == 3) ? 1 : 2);   // [x0, x2, x2, x1]
    return x[(t * 3 + p) * M_DIM + m];
}

// ---- 1) prep: build x B-fragments (mma layout, bf16 hi/lo); mark+compact nodes ----
__global__ void k_prep(const float* __restrict__ x,
                       const int* __restrict__ node_in,
                       const int* __restrict__ top, const int* __restrict__ bottom,
                       const int* __restrict__ left, const int* __restrict__ right) {
    if (blockIdx.x < 64) {
        int id = blockIdx.x * 256 + threadIdx.x;   // 16384 = 256 ks * 2 ntile * 32 lanes
        int ks = id >> 6;
        int ln = id & 31;
        int t  = ((id >> 5) & 1) * 8 + (ln >> 2);  // n index = t
        int k0 = ks * 16 + 2 * (ln & 3);
        float v0 = xval(x, t, k0),     v1 = xval(x, t, k0 + 1);
        float v8 = xval(x, t, k0 + 8), v9 = xval(x, t, k0 + 9);
        uint32_t b0h = bf2(v1, v0);
        uint32_t b1h = bf2(v9, v8);
        uint32_t b0l = bf2(v1 - hi16f(b0h), v0 - lo16f(b0h));
        uint32_t b1l = bf2(v9 - hi16f(b1h), v8 - lo16f(b1h));
        g_xfrag[id] = make_uint4(b0h, b1h, b0l, b1l);
    } else {
        int idx = (blockIdx.x - 64) * 256 + threadIdx.x;
        int v = 0;
        if      (idx < N_IN)           v = node_in[idx];
        else if (idx < N_IN + 1*N_B)   v = top[idx - N_IN];
        else if (idx < N_IN + 2*N_B)   v = bottom[idx - N_IN - 1*N_B];
        else if (idx < N_IN + 3*N_B)   v = left[idx - N_IN - 2*N_B];
        else if (idx < N_IN + 4*N_B)   v = right[idx - N_IN - 3*N_B];
        if (v > 0 && atomicExch(&g_mask[v - 1], 1) == 0)
            g_list[atomicAdd(&g_count, 1)] = v - 1;
    }
}

// ---- 2) HMMA GEMM, 3-term bf16 split, warp-autonomous (NO CTA barriers) ----
// Warp w owns nodes [8w, 8w+8) and a private 8KB smem region (2 bufs x 4KB:
// hi 2KB + lo 2KB, 16 rows x 128B). Lane = (j0=lane>>3 node-in-group,
// l8=lane&7 16B piece): each LDG.128 warp-instr reads 4 nodes x 128B
// contiguous (4 wf, optimal). STS.32 addresses precomputed; bank-conflict-free.
// Only __syncwarp between store and ldmatrix phases.
#define CHUNK_STEP(C_, CUR, NXT, XCUR, XNXT)                                     \
{                                                                                \
    const int cn_ = ((C_) + 1) & 63;                                             \
    _Pragma("unroll")                                                            \
    for (int g = 0; g < 2; ++g)                                                  \
        _Pragma("unroll")                                                        \
        for (int p = 0; p < 4; ++p)                                              \
            NXT[g*4+p] = __ldcs(wptr[g] + cn_ * 32 + p * 8);                     \
    _Pragma("unroll")                                                            \
    for (int q = 0; q < 8; ++q) XNXT[q] = xfp[cn_ * 256 + q * 32];               \
    const uint32_t hb_ = wsm + (uint32_t)(((C_) & 1) * 4096);                    \
    _Pragma("unroll")                                                            \
    for (int g = 0; g < 2; ++g)                                                  \
        _Pragma("unroll")                                                        \
        for (int p = 0; p < 4; ++p) {                                            \
            float4 f = CUR[g*4+p];   /* (w[i][0],w[i][1],w[i+1][0],w[i+1][1]) */ \
            uint32_t h0 = bf2(f.z, f.x);                                         \
            uint32_t l0 = bf2(f.z - hi16f(h0), f.x - lo16f(h0));                 \
            uint32_t h1 = bf2(f.w, f.y);                                         \
            uint32_t l1 = bf2(f.w - hi16f(h1), f.y - lo16f(h1));                 \
            uint32_t a0 = hb_ + st0[g*4+p], a1 = hb_ + st1[g*4+p];               \
            sts32(a0, h0); sts32(a0 + 2048u, l0);                                \
            sts32(a1, h1); sts32(a1 + 2048u, l1);                                \
        }                                                                        \
    __syncwarp();                                                                \
    _Pragma("unroll")                                                            \
    for (int ks = 0; ks < 4; ++ks) {                                             \
        uint32_t adr = hb_ + lds_adr[ks];                                        \
        uint32_t a0, a1, a2, a3, q0, q1, q2, q3;                                 \
        ldsm4(a0, a1, a2, a3, adr);              /* hi fragment */               \
        ldsm4(q0, q1, q2, q3, adr + 2048u);      /* lo fragment */               \
        _Pragma("unroll")                                                        \
        for (int nt = 0; nt < 2; ++nt) {                                         \
            uint4 bf = XCUR[ks * 2 + nt];                                        \
            mmabf(acc[nt], a0, a1, a2, a3, bf.x, bf.y);                          \
            mmabf(acc[nt], a0, a1, a2, a3, bf.z, bf.w);                          \
            mmabf(acc[nt], q0, q1, q2, q3, bf.x, bf.y);                          \
        }                                                                        \
    }                                                                            \
    __syncwarp();                                                                \
}

__global__ void __launch_bounds__(128)
k_mma(const float* __restrict__ weight) {
    extern __shared__ __align__(16) char dynraw[];
    const int count = g_count;
    const int base = blockIdx.x * NPC;
    if (base >= count) return;

    const int tid = threadIdx.x;
    const int nodesHere = (count - base < NPC) ? (count - base) : NPC;
    const int wrp = tid >> 5, lane = tid & 31;
    const int j0 = lane >> 3, l8 = lane & 7;
    const uint32_t wsm = s2u(dynraw) + (uint32_t)wrp * 8192u;   // warp-private 8KB

    // node pointers + precomputed swizzled STS addresses (loop-invariant)
    const float4* wptr[2];
    uint32_t st0[8], st1[8];
    #pragma unroll
    for (int g = 0; g < 2; ++g) {
        int nl = 8 * wrp + 4 * g + j0;
        int node = g_list[base + (nl < nodesHere ? nl : nodesHere - 1)];
        wptr[g] = (const float4*)weight + (size_t)node * 2048 + l8;
        uint32_t r0 = (uint32_t)(8 * g + 2 * j0);   // local tile rows
        #pragma unroll
        for (int p = 0; p < 4; ++p) {
            uint32_t bc = (uint32_t)(32 * p + 4 * l8);
            st0[g*4+p] = swz(r0,     bc);
            st1[g*4+p] = swz(r0 + 1, bc);
        }
    }
    // ldmatrix addresses (loop-invariant; rows local 0..15)
    const int m = lane >> 3;
    const uint32_t lrow = (uint32_t)(((m & 1) << 3) + (lane & 7));
    const int kbofs = m >> 1;
    uint32_t lds_adr[4];
    #pragma unroll
    for (int ks = 0; ks < 4; ++ks)
        lds_adr[ks] = swz(lrow, (uint32_t)((2 * ks + kbofs) << 4));
    const uint4* __restrict__ xfp = g_xfrag + lane;

    float acc[2][4] = {{0.f,0.f,0.f,0.f},{0.f,0.f,0.f,0.f}};
    float4 rA[8], rB[8];
    uint4  xfA[8], xfB[8];
    #pragma unroll
    for (int g = 0; g < 2; ++g)
        #pragma unroll
        for (int p = 0; p < 4; ++p) rA[g*4+p] = __ldcs(wptr[g] + p * 8);   // chunk 0
    #pragma unroll
    for (int q = 0; q < 8; ++q) xfA[q] = xfp[q * 32];                      // chunk 0

    #pragma unroll 1
    for (int c = 0; c < NCHUNK; c += 2) {
        CHUNK_STEP(c,     rA, rB, xfA, xfB)
        CHUNK_STEP(c + 1, rB, rA, xfB, xfA)
    }

    // epilogue: D fragment -> g_f.  d0,d1: row g, cols 2t2,2t2+1; d2,d3: row g+8
    const int g = lane >> 2, t2 = lane & 3;
    #pragma unroll
    for (int half = 0; half < 2; ++half) {
        int row = wrp * 16 + g + half * 8;          // global-equivalent row
        int rnl = row >> 1, o = row & 1;
        int nd = g_list[base + (rnl < nodesHere ? rnl : nodesHere - 1)];
        #pragma unroll
        for (int nt = 0; nt < 2; ++nt) {
            int t = nt * 8 + 2 * t2;
            g_f[nd * 32 + 2 * t + o]       = acc[nt][half * 2 + 0];
            g_f[nd * 32 + 2 * (t + 1) + o] = acc[nt][half * 2 + 1];
        }
    }
}

// ---- 3) epilogue: ILP-4 gather (blocks 0..63) + boundary sums (block 64) ----
__global__ void k_post(const int* __restrict__ node_in,
                       const int* __restrict__ top, const int* __restrict__ bottom,
                       const int* __restrict__ left, const int* __restrict__ right,
                       float* __restrict__ out) {
    if (blockIdx.x < 64) {
        int j = blockIdx.x * 256 + threadIdx.x;
        #pragma unroll
        for (int i = 0; i < 4; ++i) {
            int e = j + i * 16384;                   // N_IN*8 = 64000 float4
            if (e < N_IN * 8) {
                int k = e >> 3, r = e & 7;
                ((float4*)out)[e] = ((const float4*)g_f)[(size_t)(node_in[k] - 1) * 8 + r];
            }
        }
    } else {
        __shared__ float ssum[4][4][16];
        const int tid = threadIdx.x;
        const int ch = tid >> 6, rt = tid & 63, r = rt >> 4, t = rt & 15;
        const int* arr = (r == 0) ? top : (r == 1) ? bottom : (r == 2) ? left : right;
        const int o = (r < 2) ? 1 : 0;
        float sum = 0.0f;
        #pragma unroll
        for (int b = 25 * ch; b < 25 * ch + 25; ++b)
            sum += g_f[(arr[b] - 1) * 32 + t * 2 + o];
        ssum[ch][r][t] = sum;
        __syncthreads();
        float* ob = out + N_IN * 32;
        if (tid < 64) {
            float v = ssum[0][r][t] + ssum[1][r][t] + ssum[2][r][t] + ssum[3][r][t];
            ssum[0][r][t] = v;
            ob[r * 16 + t] = v;
        }
        __syncthreads();
        if (tid < 32) {
            int rr = tid >> 4, tt = tid & 15;        // 0: top+bottom, 1: left+right
            ob[(4 + rr) * 16 + tt] = ssum[0][2 * rr][tt] + ssum[0][2 * rr + 1][tt];
        }
    }
}

extern "C" void kernel_launch(void* const* d_in, const int* in_sizes, int n_in,
                              void* d_out, int out_size) {
    const float* x       = (const float*)d_in[0];
    const float* weight  = (const float*)d_in[1];
    const int*   node_in = (const int*)d_in[2];
    const int*   top     = (const int*)d_in[3];
    const int*   bottom  = (const int*)d_in[4];
    const int*   left    = (const int*)d_in[5];
    const int*   right   = (const int*)d_in[6];
    float* out = (float*)d_out;
    (void)in_sizes; (void)n_in; (void)out_size;

    cudaFuncSetAttribute(k_mma, cudaFuncAttributeMaxDynamicSharedMemorySize, DYNSZ);
    k_prep<<<64 + 33, 256>>>(x, node_in, top, bottom, left, right);
    k_mma<<<(N_NODES + NPC - 1) / NPC, 128, DYNSZ>>>(weight);
    k_post<<<65, 256>>>(node_in, top, bottom, left, right, out);
}